// round 2
// baseline (speedup 1.0000x reference)
#include <cuda_runtime.h>
#include <cstdint>

// Unpool (inverse of tf.nn.max_pool_with_argmax), shape fixed by reference:
//   val  : [16, 64, 64, 128]  float32
//   mask : [16, 64, 64, 128]  int64 OR int32 (JAX x64-config dependent) —
//          flat argmax index into the unpooled tensor, batch offset included.
//   out  : [16, 128, 128, 128] float32
//
// Gather-tile formulation: each thread owns one pooled (b,h,w) position and
// 4 channels. The 2x2 pooling windows tile the output exactly, so this thread
// is the sole writer of its 2x2 (x4 channels) output window: no zeroing pass,
// no atomics. For each channel the mask selects which of the 4 window slots
// receives val; the rest get 0. All loads/stores are float4/int4 vectorized
// and warp-coalesced (32 threads = one full C=128 row per store).

#define B_  16
#define H_  64
#define W_  64
#define C_  128
#define H2_ 128
#define W2_ 128

static constexpr int       PER_BATCH = H2_ * W2_ * C_;            // 2,097,152
static constexpr long long TOT       = (long long)B_ * PER_BATCH; // 33,554,432
static constexpr int       ROW2      = W2_ * C_;                  // 16,384

__device__ int g_mask_is_i64;

// Classify the mask buffer element type at runtime. If the data is really
// int32, reading it as int64 fuses element pairs: v = m[2i] | (m[2i+1]<<32).
// Valid mask values are < 2^25 and virtually every high word is nonzero
// (it encodes h/w/c offsets), so the int64 interpretation lands far outside
// [0, TOT). 64 leading samples are decisive.
__global__ void detect_mask_dtype(const long long* __restrict__ m64) {
    int ok = 1;
    #pragma unroll 1
    for (int i = 0; i < 64; ++i) {
        long long v = m64[i];
        if (v < 0 || v >= TOT) { ok = 0; break; }
    }
    g_mask_is_i64 = ok;
}

__global__ void __launch_bounds__(256)
unpool_kernel(const float4* __restrict__ val4,
              const void*   __restrict__ mask,
              float*        __restrict__ out) {
    const int idx = blockIdx.x * blockDim.x + threadIdx.x;   // over B*H*W*(C/4)

    // Decode (b, h, w, c4), c4 fastest. C/4 = 32, W = 64, H = 64.
    const int c4 = idx & 31;
    const int w  = (idx >> 5)  & 63;
    const int h  = (idx >> 11) & 63;
    const int b  = idx >> 17;
    const int c  = c4 << 2;

    const float4 v = __ldcs(&val4[idx]);

    // Per-batch-local flat index of window slot (dh=0, dw=0), first channel.
    const int base = (2 * h) * ROW2 + (2 * w) * C_ + c;

    // Load 4 mask values, make them batch-local.
    int l0, l1, l2, l3;
    if (g_mask_is_i64) {
        const longlong2* m = (const longlong2*)mask + ((size_t)idx << 1);
        const longlong2 a  = __ldcs(&m[0]);
        const longlong2 bq = __ldcs(&m[1]);
        const long long off = (long long)b * PER_BATCH;
        l0 = (int)(a.x  - off);
        l1 = (int)(a.y  - off);
        l2 = (int)(bq.x - off);
        l3 = (int)(bq.y - off);
    } else {
        const int4 a = __ldcs(&((const int4*)mask)[idx]);
        const int off = b * PER_BATCH;
        l0 = a.x - off;
        l1 = a.y - off;
        l2 = a.z - off;
        l3 = a.w - off;
    }

    // r_j in {0, C_, ROW2, ROW2+C_} selects the window slot for channel j.
    const int r0 = l0 -  base;
    const int r1 = l1 - (base + 1);
    const int r2 = l2 - (base + 2);
    const int r3 = l3 - (base + 3);

    float4 o00, o01, o10, o11;
    o00.x = (r0 == 0)         ? v.x : 0.0f;
    o00.y = (r1 == 0)         ? v.y : 0.0f;
    o00.z = (r2 == 0)         ? v.z : 0.0f;
    o00.w = (r3 == 0)         ? v.w : 0.0f;

    o01.x = (r0 == C_)        ? v.x : 0.0f;
    o01.y = (r1 == C_)        ? v.y : 0.0f;
    o01.z = (r2 == C_)        ? v.z : 0.0f;
    o01.w = (r3 == C_)        ? v.w : 0.0f;

    o10.x = (r0 == ROW2)      ? v.x : 0.0f;
    o10.y = (r1 == ROW2)      ? v.y : 0.0f;
    o10.z = (r2 == ROW2)      ? v.z : 0.0f;
    o10.w = (r3 == ROW2)      ? v.w : 0.0f;

    o11.x = (r0 == ROW2 + C_) ? v.x : 0.0f;
    o11.y = (r1 == ROW2 + C_) ? v.y : 0.0f;
    o11.z = (r2 == ROW2 + C_) ? v.z : 0.0f;
    o11.w = (r3 == ROW2 + C_) ? v.w : 0.0f;

    float4* o = (float4*)(out + (size_t)b * PER_BATCH + (size_t)base);
    __stcs(o,                     o00);
    __stcs(o + (C_ >> 2),         o01);
    __stcs(o + (ROW2 >> 2),       o10);
    __stcs(o + ((ROW2 + C_) >> 2), o11);
}

extern "C" void kernel_launch(void* const* d_in, const int* in_sizes, int n_in,
                              void* d_out, int out_size) {
    const float4* val4 = (const float4*)d_in[0];
    const void*   mask = d_in[1];
    float*        out  = (float*)d_out;

    detect_mask_dtype<<<1, 1>>>((const long long*)mask);

    const int n_threads = B_ * H_ * W_ * (C_ / 4);  // 2,097,152
    unpool_kernel<<<n_threads / 256, 256>>>(val4, mask, out);
}

// round 4
// speedup vs baseline: 1.0035x; 1.0035x over previous
#include <cuda_runtime.h>
#include <cstdint>

// Unpool (inverse of tf.nn.max_pool_with_argmax):
//   val  : [16, 64, 64, 128]  float32
//   mask : [16, 64, 64, 128]  int64 OR int32 (JAX x64-config dependent)
//   out  : [16, 128, 128, 128] float32
//
// Gather-tile: each thread owns pooled (b,h,w) positions x 4 channels; the 2x2
// windows tile the output exactly, so the thread is sole writer of its window
// (no zero pass, no atomics). Mask selects which of the 4 slots gets val.
//
// dtype self-detection inlined: if mask is really int32, the int64 read of
// word 0 fuses m[0] | (m[1]<<32); m[1] (mask at c=1) is always >= 1, so the
// fused value >= 2^32 >> TOT = 2^25. One broadcast probe load is decisive and
// uniform across all threads.
//
// Each thread processes TWO c4-groups with front-batched loads (MLP ~4-6) to
// lift the issue/latency limit seen in ncu (no pipe above 58% at R2).

#define B_  16
#define H_  64
#define W_  64
#define C_  128
#define H2_ 128
#define W2_ 128

static constexpr int       PER_BATCH = H2_ * W2_ * C_;            // 2,097,152
static constexpr long long TOT       = (long long)B_ * PER_BATCH; // 33,554,432
static constexpr int       ROW2      = W2_ * C_;                  // 16,384

struct Loc { int l0, l1, l2, l3; };

__device__ __forceinline__ void emit(const float4 v, const Loc m, int base,
                                     int b, float* __restrict__ out) {
    const int r0 = m.l0 -  base;
    const int r1 = m.l1 - (base + 1);
    const int r2 = m.l2 - (base + 2);
    const int r3 = m.l3 - (base + 3);

    float4 o00, o01, o10, o11;
    o00.x = (r0 == 0)         ? v.x : 0.0f;
    o00.y = (r1 == 0)         ? v.y : 0.0f;
    o00.z = (r2 == 0)         ? v.z : 0.0f;
    o00.w = (r3 == 0)         ? v.w : 0.0f;

    o01.x = (r0 == C_)        ? v.x : 0.0f;
    o01.y = (r1 == C_)        ? v.y : 0.0f;
    o01.z = (r2 == C_)        ? v.z : 0.0f;
    o01.w = (r3 == C_)        ? v.w : 0.0f;

    o10.x = (r0 == ROW2)      ? v.x : 0.0f;
    o10.y = (r1 == ROW2)      ? v.y : 0.0f;
    o10.z = (r2 == ROW2)      ? v.z : 0.0f;
    o10.w = (r3 == ROW2)      ? v.w : 0.0f;

    o11.x = (r0 == ROW2 + C_) ? v.x : 0.0f;
    o11.y = (r1 == ROW2 + C_) ? v.y : 0.0f;
    o11.z = (r2 == ROW2 + C_) ? v.z : 0.0f;
    o11.w = (r3 == ROW2 + C_) ? v.w : 0.0f;

    float4* o = (float4*)(out + (size_t)b * PER_BATCH + (size_t)base);
    __stcs(o,                      o00);
    __stcs(o + (C_ >> 2),          o01);
    __stcs(o + (ROW2 >> 2),        o10);
    __stcs(o + ((ROW2 + C_) >> 2), o11);
}

__device__ __forceinline__ int decode_base(int idx, int& b) {
    const int c4 = idx & 31;          // C/4 = 32
    const int w  = (idx >> 5)  & 63;
    const int h  = (idx >> 11) & 63;
    b            = idx >> 17;
    return (2 * h) * ROW2 + (2 * w) * C_ + (c4 << 2);
}

__global__ void __launch_bounds__(256)
unpool_kernel(const float4* __restrict__ val4,
              const void*   __restrict__ mask,
              float*        __restrict__ out) {
    // Inline dtype probe: read-only cached broadcast load, uniform branch.
    const long long probe = __ldg((const long long*)mask);
    const bool is_i64 = (probe >= 0) && (probe < TOT);

    // Two c4-groups per thread; consecutive 256-element tiles keep all loads
    // and stores fully coalesced within each group.
    const int idxA = blockIdx.x * 512 + threadIdx.x;
    const int idxB = idxA + 256;

    const float4 vA = val4[idxA];
    const float4 vB = val4[idxB];

    int bA, bB;
    const int baseA = decode_base(idxA, bA);
    const int baseB = decode_base(idxB, bB);

    Loc mA, mB;
    if (is_i64) {
        const longlong2* m = (const longlong2*)mask;
        const longlong2 a0 = m[(size_t)idxA * 2];
        const longlong2 a1 = m[(size_t)idxA * 2 + 1];
        const longlong2 b0 = m[(size_t)idxB * 2];
        const longlong2 b1 = m[(size_t)idxB * 2 + 1];
        const long long offA = (long long)bA * PER_BATCH;
        const long long offB = (long long)bB * PER_BATCH;
        mA = { (int)(a0.x - offA), (int)(a0.y - offA),
               (int)(a1.x - offA), (int)(a1.y - offA) };
        mB = { (int)(b0.x - offB), (int)(b0.y - offB),
               (int)(b1.x - offB), (int)(b1.y - offB) };
    } else {
        const int4 a = ((const int4*)mask)[idxA];
        const int4 c = ((const int4*)mask)[idxB];
        const int offA = bA * PER_BATCH;
        const int offB = bB * PER_BATCH;
        mA = { a.x - offA, a.y - offA, a.z - offA, a.w - offA };
        mB = { c.x - offB, c.y - offB, c.z - offB, c.w - offB };
    }

    emit(vA, mA, baseA, bA, out);
    emit(vB, mB, baseB, bB, out);
}

extern "C" void kernel_launch(void* const* d_in, const int* in_sizes, int n_in,
                              void* d_out, int out_size) {
    const float4* val4 = (const float4*)d_in[0];
    const void*   mask = d_in[1];
    float*        out  = (float*)d_out;

    const int n_elems = B_ * H_ * W_ * (C_ / 4);   // 2,097,152 c4-groups
    unpool_kernel<<<n_elems / 512, 256>>>(val4, mask, out);
}